// round 5
// baseline (speedup 1.0000x reference)
#include <cuda_runtime.h>
#include <stdint.h>

// MaxoutDynamic: per row of [nrows, 4096] fp32, zero the 2048 smallest values,
// scale survivors by 4096/2048 = 2.0. Exact rank selection (row median).
//
// Float-domain selection, 16 floats/thread in registers. FOUR seed pivots
// (+-0.0196 = +-1 sigma, +-0.0822 = +-4.2 sigma of the sample-median
// distribution) are counted DURING the global load (hidden under LDG latency;
// one barrier). Then secant iterations on the (value,count) bracket with
// early exit when count == 2048 exactly; key-space bisection fallback
// guarantees termination. Ties resolved by index (stable-argsort semantics).

#define FEAT    4096
#define KEEP    2048u
#define THREADS 256
#define EPT     16
#define NWARP   (THREADS / 32)

__device__ __forceinline__ unsigned f2key(unsigned b) {
    return b ^ (((unsigned)((int)b >> 31)) | 0x80000000u);
}
__device__ __forceinline__ float key2f(unsigned k) {
    unsigned b = (k & 0x80000000u) ? (k ^ 0x80000000u) : ~k;
    return __uint_as_float(b);
}

// One-barrier block sum (ping-pong parity buffer owned by caller).
__device__ __forceinline__ unsigned block_sum(unsigned c, unsigned* buf,
                                              int lane, int warp) {
    c = __reduce_add_sync(0xFFFFFFFFu, c);
    if (lane == 0) buf[warp] = c;
    __syncthreads();
    uint4 a = *reinterpret_cast<const uint4*>(buf);
    uint4 b = *reinterpret_cast<const uint4*>(buf + 4);
    return a.x + a.y + a.z + a.w + b.x + b.y + b.z + b.w;
}

__global__ __launch_bounds__(THREADS)
void maxout_sel_kernel(const float* __restrict__ in, float* __restrict__ out) {
    const int row  = blockIdx.x;
    const int tid  = threadIdx.x;
    const int lane = tid & 31;
    const int warp = tid >> 5;

    const float4* in4  = reinterpret_cast<const float4*>(in)  + (size_t)row * (FEAT / 4);
    float4*       out4 = reinterpret_cast<float4*>(out)       + (size_t)row * (FEAT / 4);

    __shared__ __align__(16) unsigned scnt[3][NWARP];
    int par = 0;

    const float S1 = -0.0822f, S2 = -0.0196f, S3 = 0.0196f, S4 = 0.0822f;

    // Load row; count all four seeds under the load latency.
    float v[EPT];
    unsigned c1 = 0, c2 = 0, c3 = 0, c4 = 0;
#pragma unroll
    for (int j = 0; j < 4; ++j) {
        float4 u = in4[tid + THREADS * j];
        v[4 * j + 0] = u.x; v[4 * j + 1] = u.y;
        v[4 * j + 2] = u.z; v[4 * j + 3] = u.w;
#pragma unroll
        for (int i = 0; i < 4; ++i) {
            float x = v[4 * j + i];
            c1 += (x >= S1) ? 1u : 0u;
            c2 += (x >= S2) ? 1u : 0u;
            c3 += (x >= S3) ? 1u : 0u;
            c4 += (x >= S4) ? 1u : 0u;
        }
    }
    {   // two packed reductions (counts <= 4096 = 13 bits), ONE barrier
        unsigned pa = (c1 << 13) | c2;
        unsigned pb = (c3 << 13) | c4;
        pa = __reduce_add_sync(0xFFFFFFFFu, pa);
        pb = __reduce_add_sync(0xFFFFFFFFu, pb);
        if (lane == 0) { scnt[0][warp] = pa; scnt[1][warp] = pb; }
        __syncthreads();
        uint4 a0 = *reinterpret_cast<const uint4*>(&scnt[0][0]);
        uint4 a1 = *reinterpret_cast<const uint4*>(&scnt[0][4]);
        uint4 b0 = *reinterpret_cast<const uint4*>(&scnt[1][0]);
        uint4 b1 = *reinterpret_cast<const uint4*>(&scnt[1][4]);
        unsigned ta = a0.x + a0.y + a0.z + a0.w + a1.x + a1.y + a1.z + a1.w;
        unsigned tb = b0.x + b0.y + b0.z + b0.w + b1.x + b1.y + b1.z + b1.w;
        c1 = ta >> 13; c2 = ta & 0x1FFFu;
        c3 = tb >> 13; c4 = tb & 0x1FFFu;
        par = 2;   // scnt[2] is free for the first round; we rotate 2->0->1->2...
    }

    float T = 0.0f;
    unsigned cutoff = 0u;
    bool resolved = false;

    // Pick bracket segment from the seed ladder.
    unsigned long long klo, khi;
    float vlo = 0.f, vhi = 0.f;
    unsigned c_klo, c_khi;

    if      (c1 == KEEP) { T = S1; resolved = true; klo = khi = 0; c_klo = c_khi = 0; }
    else if (c2 == KEEP) { T = S2; resolved = true; klo = khi = 0; c_klo = c_khi = 0; }
    else if (c3 == KEEP) { T = S3; resolved = true; klo = khi = 0; c_klo = c_khi = 0; }
    else if (c4 == KEEP) { T = S4; resolved = true; klo = khi = 0; c_klo = c_khi = 0; }
    else if (c1 < KEEP) {   // below S1
        klo = 0ULL;                          c_klo = FEAT;
        khi = f2key(__float_as_uint(S1));    c_khi = c1;  vhi = S1;
    } else if (c2 < KEEP) { // in [S1, S2)
        klo = f2key(__float_as_uint(S1));    c_klo = c1;  vlo = S1;
        khi = f2key(__float_as_uint(S2));    c_khi = c2;  vhi = S2;
    } else if (c3 < KEEP) { // in [S2, S3)
        klo = f2key(__float_as_uint(S2));    c_klo = c2;  vlo = S2;
        khi = f2key(__float_as_uint(S3));    c_khi = c3;  vhi = S3;
    } else if (c4 < KEEP) { // in [S3, S4)
        klo = f2key(__float_as_uint(S3));    c_klo = c3;  vlo = S3;
        khi = f2key(__float_as_uint(S4));    c_khi = c4;  vhi = S4;
    } else {                // above S4
        klo = f2key(__float_as_uint(S4));    c_klo = c4;  vlo = S4;
        khi = 0x100000000ULL;                c_khi = 0u;
    }

    int iter = 0;
    while (!resolved && khi - klo > 1ULL) {
        unsigned pk;
        if (iter < 8 && klo != 0ULL && khi != 0x100000000ULL) {
            float fr = ((float)c_klo - (float)KEEP) / ((float)c_klo - (float)c_khi);
            pk = f2key(__float_as_uint(vlo + (vhi - vlo) * fr));
        } else {
            pk = (unsigned)((klo + khi) >> 1);
        }
        if ((unsigned long long)pk <= klo) pk = (unsigned)(klo + 1ULL);
        if ((unsigned long long)pk >= khi) pk = (unsigned)(khi - 1ULL);
        float p = key2f(pk);

        unsigned c = 0;
#pragma unroll
        for (int i = 0; i < EPT; ++i) c += (v[i] >= p) ? 1u : 0u;
        c = block_sum(c, scnt[par], lane, warp);
        par = (par == 2) ? 0 : par + 1;

        if (c == KEEP) { T = p; resolved = true; break; }
        if (c > KEEP) { klo = pk; c_klo = c; vlo = p; }
        else          { khi = pk; c_khi = c; vhi = p; }
        ++iter;
    }

    if (!resolved) {
        // khi == klo + 1; c_klo = #{v >= T}.
        T = key2f((unsigned)klo);
        unsigned cGT = 0;
#pragma unroll
        for (int i = 0; i < EPT; ++i) cGT += (v[i] > T) ? 1u : 0u;
        cGT = block_sum(cGT, scnt[par], lane, warp);
        par = (par == 2) ? 0 : par + 1;

        unsigned kk = KEEP - cGT;
        unsigned E  = c_klo - cGT;
        if (E != kk) {
            unsigned clo = 0u, chi = FEAT - 1u;
            while (clo < chi) {
                unsigned d  = chi - clo;
                unsigned cm = clo + (d >> 1) + (d & 1u);
                unsigned c  = 0;
#pragma unroll
                for (int i = 0; i < EPT; ++i) {
                    unsigned idx = 4u * (unsigned)tid + 1024u * (unsigned)(i >> 2) + (unsigned)(i & 3);
                    c += (v[i] == T && idx >= cm) ? 1u : 0u;
                }
                c = block_sum(c, scnt[par], lane, warp);
                par = (par == 2) ? 0 : par + 1;
                if (c >= kk) clo = cm; else chi = cm - 1u;
            }
            cutoff = clo;
        }
    }

    // Output (cutoff is block-uniform, so the branch is uniform).
    if (cutoff == 0u) {
#pragma unroll
        for (int j = 0; j < 4; ++j) {
            float4 o;
            o.x = (v[4 * j + 0] >= T) ? v[4 * j + 0] * 2.0f : 0.0f;
            o.y = (v[4 * j + 1] >= T) ? v[4 * j + 1] * 2.0f : 0.0f;
            o.z = (v[4 * j + 2] >= T) ? v[4 * j + 2] * 2.0f : 0.0f;
            o.w = (v[4 * j + 3] >= T) ? v[4 * j + 3] * 2.0f : 0.0f;
            out4[tid + THREADS * j] = o;
        }
    } else {
#pragma unroll
        for (int j = 0; j < 4; ++j) {
            unsigned ib = 4u * (unsigned)tid + 1024u * (unsigned)j;
            float4 o;
            float* po = &o.x;
#pragma unroll
            for (int i = 0; i < 4; ++i) {
                float x = v[4 * j + i];
                bool keep = (x > T) || (x == T && (ib + i) >= cutoff);
                po[i] = keep ? x * 2.0f : 0.0f;
            }
            out4[tid + THREADS * j] = o;
        }
    }
}

extern "C" void kernel_launch(void* const* d_in, const int* in_sizes, int n_in,
                              void* d_out, int out_size) {
    const float* feat = (const float*)d_in[0];
    float* out = (float*)d_out;
    int nrows = in_sizes[0] / FEAT;
    maxout_sel_kernel<<<nrows, THREADS>>>(feat, out);
}